// round 12
// baseline (speedup 1.0000x reference)
#include <cuda_runtime.h>

#define NEG_PENALTY 0.03f
#define BATCH 64
#define NCLS  2048
#define LL    1024
#define NT    1024
#define GRID  BATCH
#define NB    1024
#define FULLM 0xffffffffu
#define BMIN   (-6.5f)
#define BSCALE (1024.0f / 13.0f)   // buckets cover [-6.5, 6.5]; clamp handles tails

__device__ float    g_accum  = 0.0f;
__device__ unsigned g_ticket = 0;    // self-resetting via atomicInc wrap

__device__ __forceinline__ int bucket_of(float v) {
    int bkt = (int)((v - BMIN) * BSCALE);
    return min(max(bkt, 0), NB - 1);
}

__global__ __launch_bounds__(NT)
void ranking_loss_kernel(const float* __restrict__ ranks,
                         const int*   __restrict__ labels,
                         const void*  __restrict__ ids_raw,
                         float* __restrict__ out)
{
    __shared__ float s_rank[NCLS];     // staged ranks row (coalesced)
    __shared__ char  s_lab8[NCLS];     // staged labels row
    __shared__ int   s_bcnt[NB];       // per-bucket pos count
    __shared__ float s_bsum[NB];       // per-bucket pos value sum
    __shared__ int   s_boff[NB + 1];   // exclusive count offsets
    __shared__ float s_bS[NB];         // exclusive sum offsets
    __shared__ float s_vals[LL];       // bucket-grouped pos values
    __shared__ int   s_iscan[32];
    __shared__ float s_fscan[32];
    __shared__ float s_warp[32];

    const int b    = blockIdx.x;       // one CTA per batch
    const int tid  = threadIdx.x;
    const int lane = tid & 31;
    const int wid  = tid >> 5;

    // --- dtype sniff: int64 ids have zero high words at odd 32-bit indices ---
    const int* w32 = (const int*)ids_raw;
    const bool is64 = ((w32[201] | w32[401] | w32[601] | w32[801]) == 0);
    const long long* w64 = (const long long*)ids_raw;

    // ---- all-independent loads (MLP=5): id + coalesced row staging ----
    int   id  = is64 ? (int)w64[tid] : w32[tid];
    const float* rrow = ranks  + b * NCLS;
    const int*   lrow = labels + b * NCLS;
    float rv0 = rrow[tid];
    float rv1 = rrow[tid + LL];
    int   lv0 = lrow[tid];
    int   lv1 = lrow[tid + LL];

    s_bcnt[tid]      = 0;
    s_bsum[tid]      = 0.0f;
    s_rank[tid]      = rv0;
    s_rank[tid + LL] = rv1;
    s_lab8[tid]      = (char)lv0;
    s_lab8[tid + LL] = (char)lv1;
    __syncthreads();                                  // B0

    // ---- smem gather + fused (count,sum) histogram ----
    const float r     = s_rank[id];
    const bool  ispos = (s_lab8[id] == 1);
    const float x     = r + NEG_PENALTY;              // used if neg
    const int   bkt   = bucket_of(ispos ? r : x);     // monotone map

    int sidx = 0;
    if (ispos) {
        sidx = atomicAdd(&s_bcnt[bkt], 1);
        atomicAdd(&s_bsum[bkt], r);
    }
    __syncthreads();                                  // B1

    // ---- joint block scan of (count, sum) over 1024 buckets ----
    const int   vc = s_bcnt[tid];
    const float vs = s_bsum[tid];
    int   ic = vc;
    float fs = vs;
    #pragma unroll
    for (int d = 1; d < 32; d <<= 1) {
        int   tc = __shfl_up_sync(FULLM, ic, d);
        float ts = __shfl_up_sync(FULLM, fs, d);
        if (lane >= d) { ic += tc; fs += ts; }
    }
    if (lane == 31) { s_iscan[wid] = ic; s_fscan[wid] = fs; }
    __syncthreads();                                  // B2
    if (wid == 0) {
        int   wc = s_iscan[lane];
        float ws = s_fscan[lane];
        #pragma unroll
        for (int d = 1; d < 32; d <<= 1) {
            int   tc = __shfl_up_sync(FULLM, wc, d);
            float ts = __shfl_up_sync(FULLM, ws, d);
            if (lane >= d) { wc += tc; ws += ts; }
        }
        s_iscan[lane] = wc; s_fscan[lane] = ws;
    }
    __syncthreads();                                  // B3
    const int   exc = ((wid > 0) ? s_iscan[wid - 1] : 0) + ic - vc;
    const float exs = ((wid > 0) ? s_fscan[wid - 1] : 0.0f) + fs - vs;
    s_boff[tid] = exc;
    s_bS[tid]   = exs;
    if (tid == NT - 1) s_boff[NB] = exc + vc;         // = np
    __syncthreads();                                  // B4

    // ---- bucket-grouped scatter of pos values ----
    if (ispos) s_vals[s_boff[bkt] + sidx] = r;
    __syncthreads();                                  // B5

    // ---- per-neg closed form: (k0+c)*x - (S0+s) ----
    float acc = 0.0f;
    if (!ispos) {
        const int k0 = s_boff[bkt];        // pos strictly below bucket -> < x
        const int e  = s_boff[bkt + 1];
        int c = 0; float s = 0.0f;
        for (int i = k0; i < e; i++) {     // partial bucket, ~0-3 elems
            float p = s_vals[i];
            if (p < x) { c++; s += p; }
        }
        acc = (float)(k0 + c) * x - (s_bS[bkt] + s);
    }

    // ---- block reduce (shfl trees) + scalar-accumulator tail ----
    #pragma unroll
    for (int d = 16; d >= 1; d >>= 1)
        acc += __shfl_down_sync(FULLM, acc, d);
    if (lane == 0) s_warp[wid] = acc;
    __syncthreads();                                  // B6
    if (wid == 0) {
        float a2 = s_warp[lane];
        #pragma unroll
        for (int d = 16; d >= 1; d >>= 1)
            a2 += __shfl_down_sync(FULLM, a2, d);
        if (lane == 0) {
            atomicAdd(&g_accum, a2);
            __threadfence();
            unsigned t = atomicInc(&g_ticket, GRID - 1);  // wraps at 63
            if (t == GRID - 1) {                          // last CTA finishes
                float total = atomicAdd(&g_accum, 0.0f);  // atomic read
                out[0] = total * (1.0f / (float)BATCH);
                g_accum = 0.0f;                           // reset for next call
                __threadfence();
            }
        }
    }
}

extern "C" void kernel_launch(void* const* d_in, const int* in_sizes, int n_in,
                              void* d_out, int out_size)
{
    const float* ranks  = (const float*)d_in[0];   // [B, C] f32
    const int*   labels = (const int*)d_in[1];     // [B, C] i32
    const void*  ids    = d_in[2];                 // [L] i64 or i32 (sniffed)
    float* out = (float*)d_out;                    // [1] f32

    ranking_loss_kernel<<<GRID, NT>>>(ranks, labels, ids, out);
}

// round 13
// speedup vs baseline: 1.0294x; 1.0294x over previous
#include <cuda_runtime.h>

#define NEG_PENALTY 0.03f
#define BATCH 64
#define NCLS  2048
#define LL    1024
#define NT    512
#define GRID  BATCH
#define NB    1024
#define FULLM 0xffffffffu
#define BMIN   (-6.5f)
#define BSCALE (1024.0f / 13.0f)

__device__ float    g_accum  = 0.0f;
__device__ unsigned g_ticket = 0;    // self-resetting via atomicInc wrap

__device__ __forceinline__ int bucket_of(float v) {
    int bkt = (int)((v - BMIN) * BSCALE);
    return min(max(bkt, 0), NB - 1);
}

__global__ __launch_bounds__(NT)
void ranking_loss_kernel(const float* __restrict__ ranks,
                         const int*   __restrict__ labels,
                         const void*  __restrict__ ids_raw,
                         float* __restrict__ out)
{
    __shared__ __align__(16) float s_rank[NCLS];
    __shared__ __align__(16) int   s_lab[NCLS];
    __shared__ int   s_bcnt[NB];
    __shared__ float s_bsum[NB];
    __shared__ int   s_boff[NB + 1];
    __shared__ float s_bS[NB];
    __shared__ float s_vals[LL];
    __shared__ int   s_iscan[16];
    __shared__ float s_fscan[16];
    __shared__ float s_warp[16];

    const int b    = blockIdx.x;
    const int tid  = threadIdx.x;
    const int lane = tid & 31;
    const int wid  = tid >> 5;        // 0..15

    const int* w32 = (const int*)ids_raw;
    const long long* w64 = (const long long*)ids_raw;

    // ---- ALL front loads issued in parallel (no dependency on sniff) ----
    // sniff words (uniform), default i32 ids (safe under both layouts),
    // and float4/int4 coalesced row staging.
    int sn = w32[201] | w32[401] | w32[601] | w32[801];
    int id0 = w32[tid];
    int id1 = w32[tid + NT];
    const float4* rrow4 = (const float4*)(ranks  + b * NCLS);
    const int4*   lrow4 = (const int4*)(labels + b * NCLS);
    float4 rq = rrow4[tid];
    int4   lq = lrow4[tid];

    ((float4*)s_rank)[tid] = rq;
    ((int4*)s_lab)[tid]    = lq;
    s_bcnt[tid]       = 0;  s_bcnt[tid + NT] = 0;
    s_bsum[tid]       = 0.0f; s_bsum[tid + NT] = 0.0f;

    if (sn == 0) {                     // int64 ids (fallback; never in practice)
        id0 = (int)w64[tid];
        id1 = (int)w64[tid + NT];
    }
    __syncthreads();                                  // B0

    // ---- smem gather + fused (count,sum) histogram, 2 elems/thread ----
    const float r0 = s_rank[id0];
    const float r1 = s_rank[id1];
    const bool  p0 = (s_lab[id0] == 1);
    const bool  p1 = (s_lab[id1] == 1);
    const float x0 = r0 + NEG_PENALTY;
    const float x1 = r1 + NEG_PENALTY;
    const int   b0 = bucket_of(p0 ? r0 : x0);
    const int   b1 = bucket_of(p1 ? r1 : x1);

    int si0 = 0, si1 = 0;
    if (p0) { si0 = atomicAdd(&s_bcnt[b0], 1); atomicAdd(&s_bsum[b0], r0); }
    if (p1) { si1 = atomicAdd(&s_bcnt[b1], 1); atomicAdd(&s_bsum[b1], r1); }
    __syncthreads();                                  // B1

    // ---- joint block scan of (count,sum): thread owns buckets 2t, 2t+1 ----
    const int   c0 = s_bcnt[2 * tid],     c1 = s_bcnt[2 * tid + 1];
    const float f0 = s_bsum[2 * tid],     f1 = s_bsum[2 * tid + 1];
    const int   pc = c0 + c1;
    const float pf = f0 + f1;
    int   ic = pc;   float fs = pf;
    #pragma unroll
    for (int d = 1; d < 32; d <<= 1) {
        int   tc = __shfl_up_sync(FULLM, ic, d);
        float ts = __shfl_up_sync(FULLM, fs, d);
        if (lane >= d) { ic += tc; fs += ts; }
    }
    if (lane == 31) { s_iscan[wid] = ic; s_fscan[wid] = fs; }
    __syncthreads();                                  // B2
    if (wid == 0 && lane < 16) {
        int   wc = s_iscan[lane];
        float ws = s_fscan[lane];
        #pragma unroll
        for (int d = 1; d < 16; d <<= 1) {
            int   tc = __shfl_up_sync(0xffffu, wc, d);
            float ts = __shfl_up_sync(0xffffu, ws, d);
            if (lane >= d) { wc += tc; ws += ts; }
        }
        s_iscan[lane] = wc; s_fscan[lane] = ws;
    }
    __syncthreads();                                  // B3
    const int   exc = ((wid > 0) ? s_iscan[wid - 1] : 0) + ic - pc;
    const float exs = ((wid > 0) ? s_fscan[wid - 1] : 0.0f) + fs - pf;
    s_boff[2 * tid]     = exc;
    s_boff[2 * tid + 1] = exc + c0;
    s_bS[2 * tid]       = exs;
    s_bS[2 * tid + 1]   = exs + f0;
    if (tid == NT - 1) s_boff[NB] = exc + pc;         // = np
    __syncthreads();                                  // B4

    // ---- bucket-grouped scatter of pos values ----
    if (p0) s_vals[s_boff[b0] + si0] = r0;
    if (p1) s_vals[s_boff[b1] + si1] = r1;
    __syncthreads();                                  // B5

    // ---- per-neg closed form: (k0+c)*x - (S0+s), 2 elems/thread ----
    float acc = 0.0f;
    if (!p0) {
        const int k0 = s_boff[b0], e = s_boff[b0 + 1];
        int c = 0; float s = 0.0f;
        for (int i = k0; i < e; i++) { float p = s_vals[i]; if (p < x0) { c++; s += p; } }
        acc += (float)(k0 + c) * x0 - (s_bS[b0] + s);
    }
    if (!p1) {
        const int k0 = s_boff[b1], e = s_boff[b1 + 1];
        int c = 0; float s = 0.0f;
        for (int i = k0; i < e; i++) { float p = s_vals[i]; if (p < x1) { c++; s += p; } }
        acc += (float)(k0 + c) * x1 - (s_bS[b1] + s);
    }

    // ---- block reduce (16 warps) + scalar-accumulator tail ----
    #pragma unroll
    for (int d = 16; d >= 1; d >>= 1)
        acc += __shfl_down_sync(FULLM, acc, d);
    if (lane == 0) s_warp[wid] = acc;
    __syncthreads();                                  // B6
    if (wid == 0 && lane < 16) {
        float a2 = s_warp[lane];
        #pragma unroll
        for (int d = 8; d >= 1; d >>= 1)
            a2 += __shfl_down_sync(0xffffu, a2, d);
        if (lane == 0) {
            atomicAdd(&g_accum, a2);
            __threadfence();
            unsigned t = atomicInc(&g_ticket, GRID - 1);   // wraps at 63
            if (t == GRID - 1) {                           // last CTA finishes
                float total = atomicAdd(&g_accum, 0.0f);   // atomic read
                out[0] = total * (1.0f / (float)BATCH);
                g_accum = 0.0f;                            // reset for next call
                __threadfence();
            }
        }
    }
}

extern "C" void kernel_launch(void* const* d_in, const int* in_sizes, int n_in,
                              void* d_out, int out_size)
{
    const float* ranks  = (const float*)d_in[0];   // [B, C] f32
    const int*   labels = (const int*)d_in[1];     // [B, C] i32
    const void*  ids    = d_in[2];                 // [L] i64 or i32 (sniffed)
    float* out = (float*)d_out;                    // [1] f32

    ranking_loss_kernel<<<GRID, NT>>>(ranks, labels, ids, out);
}